// round 10
// baseline (speedup 1.0000x reference)
#include <cuda_runtime.h>
#include <cstdint>

// ---------------------------------------------------------------------------
// PestDetectionSNN: two-layer LIF SNN, full fp32.
//   Pass 1: Z = event[25600,1024] @ W1[1024,128]  (fp32x2 GEMM, 2-level acc)
//   Pass 2: per-batch LIF scans + spike dots + classifier scan
//
// Numerics (frozen since R7, rel_err 4.1e-8): per output, 64 blocks of
// 16-term FMA chains in ascending k, block sums folded into a running total.
// R10 perf changes:
//  - A stored DUPLICATED in smem (float2(a,a)) so packed fp32x2 A operands
//    come straight from LDS.128 — inner loop drops from 18 to 11 issues/k-iter
//    (kills the 8 pack-MOVs).
//  - scan prefetch pipeline deepened 10 -> 20 (latency-bound, occ 10%).
// ---------------------------------------------------------------------------

#define B_  256
#define T_  100
#define D_  1024
#define H_  128
#define C_  5
#define MT  (B_ * T_)          // 25600 GEMM rows

#define DECAY1 0.90483741803595952865f
#define DECAY2 0.95122942450071400910f

// Scratch: Z = x @ W1, [25600 x 128] fp32 (13.1 MB)
__device__ float g_Z[MT * H_];

// ---- packed fp32x2 helpers (Blackwell FFMA2/FADD2 path) -------------------
__device__ __forceinline__ void fma2(unsigned long long& d,
                                     unsigned long long a,
                                     unsigned long long b,
                                     unsigned long long c) {
    asm("fma.rn.f32x2 %0, %1, %2, %3;" : "=l"(d) : "l"(a), "l"(b), "l"(c));
}
__device__ __forceinline__ void add2(unsigned long long& d,
                                     unsigned long long a,
                                     unsigned long long b) {
    asm("add.rn.f32x2 %0, %1, %2;" : "=l"(d) : "l"(a), "l"(b));
}
__device__ __forceinline__ void unpack2(unsigned long long v, float& lo, float& hi) {
    unsigned a, b;
    asm("mov.b64 {%0, %1}, %2;" : "=r"(a), "=r"(b) : "l"(v));
    lo = __uint_as_float(a);
    hi = __uint_as_float(b);
}

// ---------------------------------------------------------------------------
// Pass 1: GEMM  Z[25600,128] = A[25600,1024] @ W1[1024,128]
// BM=64, BN=64, BK=16, 256 threads, 4x4 microtile, double-buffered smem.
// A stored duplicated: As row holds [a0,a0,a1,a1,...,a63,a63] (128 floats,
// row stride 132 for alignment+banks). Grid = 400 x 2 = 800 CTAs, 3 CTAs/SM.
// ---------------------------------------------------------------------------
__global__ __launch_bounds__(256, 3) void snn_gemm_kernel(
    const float* __restrict__ A, const float* __restrict__ W1)
{
    // row stride 132 floats = 528 B = 33*16 -> every row base 16B-aligned
    __shared__ __align__(16) float As[2][16][132];  // duplicated A pairs
    __shared__ __align__(16) float Bs[2][16][64];   // Bs[k][n]

    const int tid = threadIdx.x;
    const int bx  = blockIdx.x;
    const int m0  = (bx >> 1) * 64;
    const int n0  = (bx & 1) * 64;

    // A load map: 64 rows x 4 float4-cols -> 1 float4 / thread
    const int ar = tid >> 2;            // 0..63
    const int ac = (tid & 3) << 2;      // 0,4,8,12
    // B load map: 16 rows x 16 float4-cols -> 1 float4 / thread
    const int br = tid >> 4;            // 0..15
    const int bc = (tid & 15) << 2;     // 0..60
    // compute map: 16x16 threads, each owns 4 (M) x 4 (N)
    const int tx = tid & 15;            // n = tx*4
    const int ty = tid >> 4;            // m = ty*4

    const float* Aptr = A  + (size_t)(m0 + ar) * D_ + ac;
    const float* Bptr = W1 + br * H_ + n0 + bc;

    // prologue: k-block 0 into buffer 0
    float4 aR = *(const float4*)(Aptr);
    float4 bR = *(const float4*)(Bptr);

    *(float2*)&As[0][ac + 0][ar << 1] = make_float2(aR.x, aR.x);
    *(float2*)&As[0][ac + 1][ar << 1] = make_float2(aR.y, aR.y);
    *(float2*)&As[0][ac + 2][ar << 1] = make_float2(aR.z, aR.z);
    *(float2*)&As[0][ac + 3][ar << 1] = make_float2(aR.w, aR.w);
    *(float4*)&Bs[0][br][bc] = bR;
    __syncthreads();

    unsigned long long accT[4][2];   // running totals (level 2): 4 M x 2 pairs
#pragma unroll
    for (int m = 0; m < 4; m++) { accT[m][0] = 0ull; accT[m][1] = 0ull; }

    int buf = 0;
    const int NKB = D_ / 16;  // 64
    for (int kb = 0; kb < NKB; kb++) {
        if (kb < NKB - 1) {
            aR = *(const float4*)(Aptr + (kb + 1) * 16);
            bR = *(const float4*)(Bptr + (size_t)(kb + 1) * 16 * H_);
        }

        unsigned long long accB[4][2];   // per-block 16-term chains (level 1)
#pragma unroll
        for (int m = 0; m < 4; m++) { accB[m][0] = 0ull; accB[m][1] = 0ull; }

#pragma unroll
        for (int k = 0; k < 16; k++) {
            // packed A pairs straight from smem: a2[m] = (A[m], A[m])
            ulonglong2 ap0 = *(const ulonglong2*)&As[buf][k][ty << 3];
            ulonglong2 ap1 = *(const ulonglong2*)&As[buf][k][(ty << 3) + 4];
            ulonglong2 bv  = *(const ulonglong2*)&Bs[buf][k][tx << 2];

            fma2(accB[0][0], ap0.x, bv.x, accB[0][0]);
            fma2(accB[0][1], ap0.x, bv.y, accB[0][1]);
            fma2(accB[1][0], ap0.y, bv.x, accB[1][0]);
            fma2(accB[1][1], ap0.y, bv.y, accB[1][1]);
            fma2(accB[2][0], ap1.x, bv.x, accB[2][0]);
            fma2(accB[2][1], ap1.x, bv.y, accB[2][1]);
            fma2(accB[3][0], ap1.y, bv.x, accB[3][0]);
            fma2(accB[3][1], ap1.y, bv.y, accB[3][1]);
        }

        // fold block sums into running totals
#pragma unroll
        for (int m = 0; m < 4; m++) {
            add2(accT[m][0], accT[m][0], accB[m][0]);
            add2(accT[m][1], accT[m][1], accB[m][1]);
        }

        if (kb < NKB - 1) {
            const int nb = buf ^ 1;
            *(float2*)&As[nb][ac + 0][ar << 1] = make_float2(aR.x, aR.x);
            *(float2*)&As[nb][ac + 1][ar << 1] = make_float2(aR.y, aR.y);
            *(float2*)&As[nb][ac + 2][ar << 1] = make_float2(aR.z, aR.z);
            *(float2*)&As[nb][ac + 3][ar << 1] = make_float2(aR.w, aR.w);
            *(float4*)&Bs[nb][br][bc] = bR;
            __syncthreads();
            buf = nb;
        }
    }

    // epilogue: write 4x4 tile (one float4 per M-row)
    float* Zp = g_Z + (size_t)(m0 + (ty << 2)) * H_ + n0 + (tx << 2);
#pragma unroll
    for (int m = 0; m < 4; m++) {
        float f0, f1, f2, f3;
        unpack2(accT[m][0], f0, f1);
        unpack2(accT[m][1], f2, f3);
        *(float4*)(Zp + m * H_) = make_float4(f0, f1, f2, f3);
    }
}

// ---------------------------------------------------------------------------
// Pass 2: per-batch LIF scans.
//   phase 1: thread h scans v1 over t with a 20-deep load prefetch pipeline;
//            spikes packed via ballot into smem bitmasks
//   phase 2: 500 (t,c) dot products of spike bitmasks with W2 columns
//   phase 3: threads 0..4 run the classifier LIF scan and write out
// ---------------------------------------------------------------------------
__global__ __launch_bounds__(128) void snn_scan_kernel(
    const float* __restrict__ b1, const float* __restrict__ W2,
    const float* __restrict__ b2, float* __restrict__ out)
{
    __shared__ unsigned s1w[T_ * 4];     // spike bitmasks: [t][warp]
    __shared__ float    W2s[H_ * C_];    // 640 floats
    __shared__ float    dd[T_ * C_];     // layer-2 drive per (t,c)

    const int b    = blockIdx.x;
    const int tid  = threadIdx.x;        // = h
    const int lane = tid & 31;
    const int warp = tid >> 5;

    for (int i = tid; i < H_ * C_; i += 128) W2s[i] = W2[i];

    // ---- phase 1: feature-layer LIF scan (chunked, MLP=20) ----
    const float b1h = b1[tid];
    const float* zp = g_Z + (size_t)b * T_ * H_ + tid;
    float v1 = 0.0f;

    float zbuf[20];
#pragma unroll
    for (int j = 0; j < 20; j++) zbuf[j] = zp[j * H_];

    for (int c = 0; c < 5; c++) {
        float znext[20];
        if (c < 4) {
#pragma unroll
            for (int j = 0; j < 20; j++)
                znext[j] = zp[(c * 20 + 20 + j) * H_];
        }
#pragma unroll
        for (int j = 0; j < 20; j++) {
            const int t = c * 20 + j;
            v1 = __fadd_rn(fmaf(v1, DECAY1, zbuf[j]), b1h);
            bool s = (v1 >= 1.0f);
            if (s) v1 = 0.0f;
            unsigned m = __ballot_sync(0xffffffffu, s);
            if (lane == 0) s1w[t * 4 + warp] = m;
        }
        if (c < 4) {
#pragma unroll
            for (int j = 0; j < 20; j++) zbuf[j] = znext[j];
        }
    }
    __syncthreads();

    // ---- phase 2: s1 @ W2 for all (t,c) ----
    for (int p = tid; p < T_ * C_; p += 128) {
        const int t = p / C_;
        const int c = p - t * C_;
        float sum = 0.0f;
#pragma unroll
        for (int w = 0; w < 4; w++) {
            const unsigned msk = s1w[t * 4 + w];
            const float* wp = &W2s[w * 32 * C_ + c];
#pragma unroll
            for (int bit = 0; bit < 32; bit++) {
                if (msk & (1u << bit)) sum = __fadd_rn(sum, wp[bit * C_]);
            }
        }
        dd[p] = sum;
    }
    __syncthreads();

    // ---- phase 3: classifier LIF scan ----
    if (tid < C_) {
        const float b2c = b2[tid];
        float v2 = 0.0f, acc = 0.0f;
        for (int t = 0; t < T_; t++) {
            v2 = __fadd_rn(fmaf(v2, DECAY2, dd[t * C_ + tid]), b2c);
            if (v2 >= 1.0f) { acc += 1.0f; v2 = 0.0f; }
        }
        out[b * C_ + tid] = acc / (float)T_;
    }
}

// ---------------------------------------------------------------------------
// kernel_launch
// inputs: event_stream[256,100,1024] f32, W1[1024,128], b1[128], W2[128,5], b2[5]
// output: [256,5] f32
// ---------------------------------------------------------------------------
extern "C" void kernel_launch(void* const* d_in, const int* in_sizes, int n_in,
                              void* d_out, int out_size)
{
    const float* ev = (const float*)d_in[0];
    const float* W1 = (const float*)d_in[1];
    const float* b1 = (const float*)d_in[2];
    const float* W2 = (const float*)d_in[3];
    const float* b2 = (const float*)d_in[4];
    float* out = (float*)d_out;

    snn_gemm_kernel<<<(MT / 64) * 2, 256>>>(ev, W1);
    snn_scan_kernel<<<B_, 128>>>(b1, W2, b2, out);
}

// round 11
// speedup vs baseline: 1.3308x; 1.3308x over previous
#include <cuda_runtime.h>
#include <cstdint>

// ---------------------------------------------------------------------------
// PestDetectionSNN: two-layer LIF SNN.
//   Pass 1: Z = event[25600,1024] @ W1[1024,128] via 3xTF32 tensor-core GEMM
//           (a = hi + lo tf32 splits; products hihi + lohi + hilo in fp32
//            mma accumulators; 2-level fold every 256 k)
//   Pass 2: per-batch LIF scans + spike dots + classifier scan (unchanged)
//
// Rationale: scalar FFMA roofline is 186us (R9 measured 188; fp32x2 is
// cracked to 2xFFMA on sm_103). Tensor cores are the only path below it.
// 3xTF32 error budget: dropped lo*lo ~6e-8, fp32 acc ~1e-7 -> tighter than
// the R7 scheme that passed with zero spike flips.
// ---------------------------------------------------------------------------

#define B_  256
#define T_  100
#define D_  1024
#define H_  128
#define C_  5
#define MT  (B_ * T_)          // 25600 GEMM rows

#define DECAY1 0.90483741803595952865f
#define DECAY2 0.95122942450071400910f

// Scratch: Z = x @ W1, [25600 x 128] fp32 (13.1 MB)
__device__ float g_Z[MT * H_];

// ---- tf32 split helpers ---------------------------------------------------
__device__ __forceinline__ float to_tf32(float x) {
    unsigned r;
    asm("cvt.rna.tf32.f32 %0, %1;" : "=r"(r) : "r"(__float_as_uint(x)));
    return __uint_as_float(r);
}

// mma.sync m16n8k8 tf32, D += A*B (C==D registers)
#define MMA_TF32(d, a, b)                                                   \
    asm volatile(                                                           \
        "mma.sync.aligned.m16n8k8.row.col.f32.tf32.tf32.f32 "               \
        "{%0,%1,%2,%3}, {%4,%5,%6,%7}, {%8,%9}, {%0,%1,%2,%3};"             \
        : "+f"((d)[0]), "+f"((d)[1]), "+f"((d)[2]), "+f"((d)[3])            \
        : "r"((a)[0]), "r"((a)[1]), "r"((a)[2]), "r"((a)[3]),               \
          "r"((b)[0]), "r"((b)[1]))

// ---------------------------------------------------------------------------
// Pass 1: tensor-core GEMM. BM=64, BN=128(all H), BK=16, 256 thr (8 warps).
// Warp grid 2(M) x 4(N); warp tile 32x32 -> per warp 2 m16-tiles x 4 n8-tiles.
// smem [row][k] layout, row stride 20 floats (80B: 16B-aligned rows,
// conflict-free fragment loads: banks (20g + l4) mod 32 all distinct).
// Grid = 400 CTAs.
// ---------------------------------------------------------------------------
__global__ __launch_bounds__(256) void snn_gemm_tc(
    const float* __restrict__ A, const float* __restrict__ W1)
{
    __shared__ __align__(16) float As_hi[64][20];
    __shared__ __align__(16) float As_lo[64][20];
    __shared__ __align__(16) float Bs_hi[128][20];
    __shared__ __align__(16) float Bs_lo[128][20];

    const int tid  = threadIdx.x;
    const int m0   = blockIdx.x * 64;
    const int lane = tid & 31;
    const int wid  = tid >> 5;
    const int g    = lane >> 2;     // group id 0..7
    const int l4   = lane & 3;      // thread-in-group
    const int wm   = wid >> 2;      // warp M index 0..1 (32 rows each)
    const int wn   = wid & 3;       // warp N index 0..3 (32 cols each)

    // global load maps
    const int am  = tid >> 2;            // A row 0..63
    const int akc = (tid & 3) << 2;      // A k-col 0,4,8,12
    const int bk  = tid >> 4;            // B k-row 0..15
    const int bnc = (tid & 15) << 3;     // B n-col 0..120
    const int rot = tid & 7;             // store rotation (bank spread)

    const float* Ap = A  + (size_t)(m0 + am) * D_ + akc;
    const float* Bp = W1 + bk * H_ + bnc;

    // prefetch kb=0
    float4 a4  = *(const float4*)Ap;
    float4 b40 = *(const float4*)Bp;
    float4 b41 = *(const float4*)(Bp + 4);

    float accT[2][4][4] = {};   // running totals
    float accB[2][4][4] = {};   // per-superblock (256 k) accumulators

    const int NKB = D_ / 16;    // 64
    for (int kb = 0; kb < NKB; kb++) {
        // ---- convert staged regs to tf32 hi/lo and store to smem ----
        {
            float av[4] = {a4.x, a4.y, a4.z, a4.w};
            float hi[4], lo[4];
#pragma unroll
            for (int i = 0; i < 4; i++) {
                hi[i] = to_tf32(av[i]);
                lo[i] = to_tf32(av[i] - hi[i]);
            }
            *(float4*)&As_hi[am][akc] = make_float4(hi[0], hi[1], hi[2], hi[3]);
            *(float4*)&As_lo[am][akc] = make_float4(lo[0], lo[1], lo[2], lo[3]);

            float bv[8] = {b40.x, b40.y, b40.z, b40.w,
                           b41.x, b41.y, b41.z, b41.w};
#pragma unroll
            for (int jj = 0; jj < 8; jj++) {
                int j = (jj + rot) & 7;          // rotate to spread banks
                float h = to_tf32(bv[j]);
                Bs_hi[bnc + j][bk] = h;
                Bs_lo[bnc + j][bk] = to_tf32(bv[j] - h);
            }
        }
        __syncthreads();

        // ---- prefetch next kb ----
        if (kb < NKB - 1) {
            a4  = *(const float4*)(Ap + (kb + 1) * 16);
            b40 = *(const float4*)(Bp + (size_t)(kb + 1) * 16 * H_);
            b41 = *(const float4*)(Bp + (size_t)(kb + 1) * 16 * H_ + 4);
        }

        // ---- compute: 2 k8 steps ----
#pragma unroll
        for (int k8 = 0; k8 < 16; k8 += 8) {
            unsigned ah[2][4], al[2][4];
#pragma unroll
            for (int mi = 0; mi < 2; mi++) {
                const int mr = wm * 32 + mi * 16;
                ah[mi][0] = __float_as_uint(As_hi[mr + g    ][k8 + l4    ]);
                ah[mi][1] = __float_as_uint(As_hi[mr + g + 8][k8 + l4    ]);
                ah[mi][2] = __float_as_uint(As_hi[mr + g    ][k8 + l4 + 4]);
                ah[mi][3] = __float_as_uint(As_hi[mr + g + 8][k8 + l4 + 4]);
                al[mi][0] = __float_as_uint(As_lo[mr + g    ][k8 + l4    ]);
                al[mi][1] = __float_as_uint(As_lo[mr + g + 8][k8 + l4    ]);
                al[mi][2] = __float_as_uint(As_lo[mr + g    ][k8 + l4 + 4]);
                al[mi][3] = __float_as_uint(As_lo[mr + g + 8][k8 + l4 + 4]);
            }
            unsigned b[4][2];
#pragma unroll
            for (int ni = 0; ni < 4; ni++) {
                const int nr = wn * 32 + ni * 8 + g;
                b[ni][0] = __float_as_uint(Bs_hi[nr][k8 + l4    ]);
                b[ni][1] = __float_as_uint(Bs_hi[nr][k8 + l4 + 4]);
            }
            // hi*hi
#pragma unroll
            for (int mi = 0; mi < 2; mi++)
#pragma unroll
                for (int ni = 0; ni < 4; ni++)
                    MMA_TF32(accB[mi][ni], ah[mi], b[ni]);
            // lo*hi
#pragma unroll
            for (int mi = 0; mi < 2; mi++)
#pragma unroll
                for (int ni = 0; ni < 4; ni++)
                    MMA_TF32(accB[mi][ni], al[mi], b[ni]);
            // hi*lo (reload B as lo)
#pragma unroll
            for (int ni = 0; ni < 4; ni++) {
                const int nr = wn * 32 + ni * 8 + g;
                b[ni][0] = __float_as_uint(Bs_lo[nr][k8 + l4    ]);
                b[ni][1] = __float_as_uint(Bs_lo[nr][k8 + l4 + 4]);
            }
#pragma unroll
            for (int mi = 0; mi < 2; mi++)
#pragma unroll
                for (int ni = 0; ni < 4; ni++)
                    MMA_TF32(accB[mi][ni], ah[mi], b[ni]);
        }

        // ---- 2-level fold every 16 kb (= 256 k) ----
        if ((kb & 15) == 15) {
#pragma unroll
            for (int mi = 0; mi < 2; mi++)
#pragma unroll
                for (int ni = 0; ni < 4; ni++)
#pragma unroll
                    for (int j = 0; j < 4; j++) {
                        accT[mi][ni][j] = __fadd_rn(accT[mi][ni][j],
                                                    accB[mi][ni][j]);
                        accB[mi][ni][j] = 0.0f;
                    }
        }
        __syncthreads();
    }

    // ---- epilogue: write fragments to g_Z ----
#pragma unroll
    for (int mi = 0; mi < 2; mi++) {
        const int row0 = m0 + wm * 32 + mi * 16 + g;
#pragma unroll
        for (int ni = 0; ni < 4; ni++) {
            const int col = wn * 32 + ni * 8 + 2 * l4;
            *(float2*)&g_Z[(size_t)row0 * H_ + col] =
                make_float2(accT[mi][ni][0], accT[mi][ni][1]);
            *(float2*)&g_Z[(size_t)(row0 + 8) * H_ + col] =
                make_float2(accT[mi][ni][2], accT[mi][ni][3]);
        }
    }
}

// ---------------------------------------------------------------------------
// Pass 2: per-batch LIF scans (unchanged from R10; 13.9us).
// ---------------------------------------------------------------------------
__global__ __launch_bounds__(128) void snn_scan_kernel(
    const float* __restrict__ b1, const float* __restrict__ W2,
    const float* __restrict__ b2, float* __restrict__ out)
{
    __shared__ unsigned s1w[T_ * 4];     // spike bitmasks: [t][warp]
    __shared__ float    W2s[H_ * C_];    // 640 floats
    __shared__ float    dd[T_ * C_];     // layer-2 drive per (t,c)

    const int b    = blockIdx.x;
    const int tid  = threadIdx.x;        // = h
    const int lane = tid & 31;
    const int warp = tid >> 5;

    for (int i = tid; i < H_ * C_; i += 128) W2s[i] = W2[i];

    // ---- phase 1: feature-layer LIF scan (chunked, MLP=20) ----
    const float b1h = b1[tid];
    const float* zp = g_Z + (size_t)b * T_ * H_ + tid;
    float v1 = 0.0f;

    float zbuf[20];
#pragma unroll
    for (int j = 0; j < 20; j++) zbuf[j] = zp[j * H_];

    for (int c = 0; c < 5; c++) {
        float znext[20];
        if (c < 4) {
#pragma unroll
            for (int j = 0; j < 20; j++)
                znext[j] = zp[(c * 20 + 20 + j) * H_];
        }
#pragma unroll
        for (int j = 0; j < 20; j++) {
            const int t = c * 20 + j;
            v1 = __fadd_rn(fmaf(v1, DECAY1, zbuf[j]), b1h);
            bool s = (v1 >= 1.0f);
            if (s) v1 = 0.0f;
            unsigned m = __ballot_sync(0xffffffffu, s);
            if (lane == 0) s1w[t * 4 + warp] = m;
        }
        if (c < 4) {
#pragma unroll
            for (int j = 0; j < 20; j++) zbuf[j] = znext[j];
        }
    }
    __syncthreads();

    // ---- phase 2: s1 @ W2 for all (t,c) ----
    for (int p = tid; p < T_ * C_; p += 128) {
        const int t = p / C_;
        const int c = p - t * C_;
        float sum = 0.0f;
#pragma unroll
        for (int w = 0; w < 4; w++) {
            const unsigned msk = s1w[t * 4 + w];
            const float* wp = &W2s[w * 32 * C_ + c];
#pragma unroll
            for (int bit = 0; bit < 32; bit++) {
                if (msk & (1u << bit)) sum = __fadd_rn(sum, wp[bit * C_]);
            }
        }
        dd[p] = sum;
    }
    __syncthreads();

    // ---- phase 3: classifier LIF scan ----
    if (tid < C_) {
        const float b2c = b2[tid];
        float v2 = 0.0f, acc = 0.0f;
        for (int t = 0; t < T_; t++) {
            v2 = __fadd_rn(fmaf(v2, DECAY2, dd[t * C_ + tid]), b2c);
            if (v2 >= 1.0f) { acc += 1.0f; v2 = 0.0f; }
        }
        out[b * C_ + tid] = acc / (float)T_;
    }
}

// ---------------------------------------------------------------------------
// kernel_launch
// inputs: event_stream[256,100,1024] f32, W1[1024,128], b1[128], W2[128,5], b2[5]
// output: [256,5] f32
// ---------------------------------------------------------------------------
extern "C" void kernel_launch(void* const* d_in, const int* in_sizes, int n_in,
                              void* d_out, int out_size)
{
    const float* ev = (const float*)d_in[0];
    const float* W1 = (const float*)d_in[1];
    const float* b1 = (const float*)d_in[2];
    const float* W2 = (const float*)d_in[3];
    const float* b2 = (const float*)d_in[4];
    float* out = (float*)d_out;

    snn_gemm_tc<<<MT / 64, 256>>>(ev, W1);
    snn_scan_kernel<<<B_, 128>>>(b1, W2, b2, out);
}